// round 13
// baseline (speedup 1.0000x reference)
#include <cuda_runtime.h>
#include <cuda_fp16.h>
#include <cstdint>
#include <math.h>

#define BATCH 2048
#define UNITS 768
#define IND   96
#define GATES 3072
#define STEPS 64
#define TIN   24

#define MT 128
#define NTILE 128          /* 32 units x 4 gates (reorder r' = u*4+q) */
#define MTILES 16
#define NTILES 24
#define TPS_G  (MTILES * NTILES)   /* 384 gates tiles per step */
#define WEFF_T 256                 /* weff tickets, 12 rows each */
#define WEFF_ROWS 12
#define TOTAL_TICKETS (WEFF_T + STEPS * TPS_G)   /* 256 + 24576 = 24832 */
#define GRID_PERSIST 296

#define KP_MAIN 768
#define NCH_MAIN 12
#define KP0 128
#define NCH0 2

/* gates smem: 3 stages x 32KB (A,B tiles of 16KB each) + bias */
#define STG_STRIDE 32768
#define T_AH 0
#define T_BH 16384
#define OFF_BIAS 98304
#define GATES_SMEM (OFF_BIAS + 512)     /* 98816 -> 2 CTAs/SM */

/* pred_all smem: 2 stages x 28KB (A 16KB + B 12KB) */
#define PSTG 28672
#define P_A  0
#define P_BH 16384
#define PRED_SMEM (2 * PSTG)            /* 57344 */

// ---------------------------------------------------------------------------
// Device globals
// ---------------------------------------------------------------------------
__device__ __half g_hist[(size_t)STEPS * BATCH * UNITS];  // h history
__device__ __half g_x0[BATCH * KP0];        // step-0 input, padded
__device__ float  g_c[BATCH * UNITS];       // cell state (written fresh at s=0)
__device__ __half g_Weff[GATES * UNITS];    // reordered W_hh + W_ih@W_d (fp16)
__device__ __half g_Wih16[GATES * KP0];     // reordered W_ih (fp16, padded)
__device__ __half g_Pdh[IND * UNITS];       // W_d fp16 (row n, col k)
__device__ float  g_b0[GATES];              // reordered b_ih + b_hh
__device__ float  g_beff[GATES];            // reordered b_ih + b_hh + W_ih@b_d
__device__ int    g_ticket;                 // global tile ticket
__device__ int    g_cnt[STEPS * MTILES];    // per-(step, m-block) completion
__device__ int    g_weffdone;               // weff tickets completed

__device__ __forceinline__ uint32_t smem_u32(const void* p) {
    uint32_t a;
    asm("{ .reg .u64 t; cvta.to.shared.u64 t, %1; cvt.u32.u64 %0, t; }" : "=r"(a) : "l"(p));
    return a;
}
__device__ __forceinline__ void cp16(uint32_t dst, const void* src) {
    asm volatile("cp.async.cg.shared.global [%0], [%1], 16;" :: "r"(dst), "l"(src));
}
__device__ __forceinline__ void ldsm4(uint32_t* r, uint32_t addr) {
    asm volatile("ldmatrix.sync.aligned.m8n8.x4.shared.b16 {%0,%1,%2,%3}, [%4];"
        : "=r"(r[0]), "=r"(r[1]), "=r"(r[2]), "=r"(r[3]) : "r"(addr));
}
__device__ __forceinline__ void mma16816(float* c, const uint32_t* a, uint32_t b0, uint32_t b1) {
    asm volatile("mma.sync.aligned.m16n8k16.row.col.f32.f16.f16.f32 "
        "{%0,%1,%2,%3}, {%4,%5,%6,%7}, {%8,%9}, {%0,%1,%2,%3};"
        : "+f"(c[0]), "+f"(c[1]), "+f"(c[2]), "+f"(c[3])
        : "r"(a[0]), "r"(a[1]), "r"(a[2]), "r"(a[3]), "r"(b0), "r"(b1));
}
// fast transcendentals (rel err ~1e-6, well under budget)
__device__ __forceinline__ float fsig(float x)  { return 1.0f / (1.0f + __expf(-x)); }
__device__ __forceinline__ float ftanh(float x) {
    float e = __expf(2.0f * x);
    return (e - 1.0f) / (e + 1.0f);
}

// ---------------------------------------------------------------------------
// prep_all: scheduler init + x0 pad + W_ih fp16 + W_d fp16 + biases.
// (no c zeroing — gates(0) epilogue writes c without reading)
// max arm = GATES*KP0 = 393216 -> grid 1536
// ---------------------------------------------------------------------------
__global__ void prep_all(const float* __restrict__ inputs,
                         const float* __restrict__ W_ih,
                         const float* __restrict__ b_ih, const float* __restrict__ b_hh,
                         const float* __restrict__ W_d, const float* __restrict__ b_d) {
    int i = blockIdx.x * blockDim.x + threadIdx.x;
    if (i == 0) { g_ticket = 0; g_weffdone = 0; }
    if (i < STEPS * MTILES) g_cnt[i] = 0;
    if (i < BATCH * KP0) {
        int b = i / KP0, k = i % KP0;
        float v = (k < IND) ? inputs[(b * TIN + (TIN - 1)) * IND + k] : 0.0f;
        g_x0[i] = __float2half_rn(v);
    }
    if (i < GATES * KP0) {
        int rp = i / KP0, k = i % KP0;
        int orig = (rp & 3) * UNITS + (rp >> 2);
        float w = (k < IND) ? W_ih[orig * IND + k] : 0.0f;
        g_Wih16[i] = __float2half_rn(w);
    }
    if (i < IND * UNITS) g_Pdh[i] = __float2half_rn(W_d[i]);
    if (i < GATES) {
        int orig = (i & 3) * UNITS + (i >> 2);
        float b0 = b_ih[orig] + b_hh[orig];
        g_b0[i] = b0;
        float be = b0;
#pragma unroll 4
        for (int j = 0; j < IND; j++) be += W_ih[orig * IND + j] * b_d[j];
        g_beff[i] = be;
    }
}

// ---------------------------------------------------------------------------
// run_persist: persistent kernel. Ticket layout:
//   [weff x256]  (each: 12 reordered W_eff rows)   -- ready immediately
//   [gates(0) x384]                                 -- needs only prep_all
//   [gates(s) x384 for s=1..63]                     -- waits cnt[s-1][m]==24
//                                                      and g_weffdone==256
// ---------------------------------------------------------------------------
__device__ __forceinline__ void load_stage_r(uint32_t sb, int stage, int kc, int tid,
                                             int bm0, int n0r, int kp,
                                             const __half* __restrict__ A,
                                             const __half* __restrict__ W) {
    uint32_t base = sb + stage * STG_STRIDE;
    int k0 = kc * 64;
#pragma unroll
    for (int i = 0; i < 4; i++) {
        int e = tid + i * 256;
        int row = e >> 3, sub = e & 7;
        uint32_t off = row * 128 + sub * 16;
        uint32_t sw = off ^ ((off >> 3) & 0x70);
        cp16(base + T_AH + sw, A + (size_t)(bm0 + row) * kp + k0 + sub * 8);
        cp16(base + T_BH + sw, W + (size_t)(n0r + row) * kp + k0 + sub * 8);
    }
    asm volatile("cp.async.commit_group;");
}

__global__ __launch_bounds__(256) void run_persist(const float* __restrict__ W_ih,
                                                   const float* __restrict__ W_hh,
                                                   const float* __restrict__ W_d) {
    extern __shared__ __align__(1024) char smem[];
    __shared__ int s_ticket;
    const uint32_t sb = smem_u32(smem);
    float* sB = (float*)(smem + OFF_BIAS);
    const int tid = threadIdx.x;
    const int wid = tid >> 5;
    const int lane = tid & 31;

    // gates warp tiling: 2 (m) x 4 (n); warp tile 64 x 32
    const int wm = wid & 1, wn = wid >> 1;
    const int ra = lane & 7, qa = lane >> 3;
    const int colsel = (qa >> 1) * 16;
    int arow[4], axor[4], browr[2], bxor[2];
#pragma unroll
    for (int mi = 0; mi < 4; mi++) {
        int r = wm * 64 + mi * 16 + ra + (qa & 1) * 8;
        arow[mi] = r * 128;
        axor[mi] = (r & 7) << 4;
    }
#pragma unroll
    for (int nb = 0; nb < 2; nb++) {
        int r = wn * 32 + nb * 16 + ra + (qa & 1) * 8;
        browr[nb] = r * 128;
        bxor[nb] = (r & 7) << 4;
    }

    for (;;) {
        if (tid == 0) s_ticket = atomicAdd(&g_ticket, 1);
        __syncthreads();
        const int ticket = s_ticket;
        if (ticket >= TOTAL_TICKETS) break;

        if (ticket < WEFF_T) {
            // ============ weff ticket: 12 reordered rows of W_eff ============
            const int rp0 = ticket * WEFF_ROWS;
            for (int e = tid; e < WEFF_ROWS * UNITS; e += 256) {
                int rp = rp0 + e / UNITS;
                int k  = e % UNITS;
                int orig = (rp & 3) * UNITS + (rp >> 2);
                float s = W_hh[orig * UNITS + k];
#pragma unroll 8
                for (int j = 0; j < IND; j++)
                    s += W_ih[orig * IND + j] * W_d[j * UNITS + k];
                g_Weff[(size_t)rp * UNITS + k] = __float2half_rn(s);
            }
            __threadfence();
            __syncthreads();
            if (tid == 0) atomicAdd(&g_weffdone, 1);
            continue;
        }

        // ================= gates tile =================
        const int gt = ticket - WEFF_T;
        const int s  = gt / TPS_G;
        const int r  = gt % TPS_G;
        const int m  = r / NTILES;
        const int nt = r % NTILES;
        const int bm0 = m * MT;
        const int n0r = nt * NTILE;

        const __half* A; const __half* W; const float* bias;
        int kp, nch;
        if (s == 0) { A = g_x0; W = g_Wih16; bias = g_b0; kp = KP0; nch = NCH0; }
        else {
            A = g_hist + (size_t)(s - 1) * BATCH * UNITS;
            W = g_Weff; bias = g_beff; kp = KP_MAIN; nch = NCH_MAIN;
        }
        __half* __restrict__ Hout = g_hist + (size_t)s * BATCH * UNITS;

        if (s > 0) {
            if (tid == 0) {
                volatile int* c = &g_cnt[(s - 1) * MTILES + m];
                while (*c < NTILES) __nanosleep(64);
                volatile int* wdone = &g_weffdone;
                while (*wdone < WEFF_T) __nanosleep(64);
            }
            __syncthreads();
            __threadfence();   // acquire
        }

        if (tid < NTILE) sB[tid] = bias[n0r + tid];

        float acc[4][4][4];
#pragma unroll
        for (int mi = 0; mi < 4; mi++)
#pragma unroll
            for (int ni = 0; ni < 4; ni++)
#pragma unroll
                for (int j = 0; j < 4; j++) acc[mi][ni][j] = 0.0f;

        load_stage_r(sb, 0, 0, tid, bm0, n0r, kp, A, W);
        load_stage_r(sb, 1, 1, tid, bm0, n0r, kp, A, W);

#pragma unroll 1
        for (int i = 0; i < nch; i++) {
            if (i + 2 < nch) {
                load_stage_r(sb, (i + 2) % 3, i + 2, tid, bm0, n0r, kp, A, W);
                asm volatile("cp.async.wait_group 2;");
            } else if (i + 1 < nch) {
                asm volatile("cp.async.wait_group 1;");
            } else {
                asm volatile("cp.async.wait_group 0;");
            }
            __syncthreads();

            uint32_t base = sb + (i % 3) * STG_STRIDE;
#pragma unroll
            for (int kk = 0; kk < 4; kk++) {
                const int colb = kk * 32 + colsel;
                uint32_t ah[4][4], bh[2][4];
#pragma unroll
                for (int mi = 0; mi < 4; mi++)
                    ldsm4(ah[mi], base + T_AH + arow[mi] + (colb ^ axor[mi]));
#pragma unroll
                for (int nb = 0; nb < 2; nb++)
                    ldsm4(bh[nb], base + T_BH + browr[nb] + (colb ^ bxor[nb]));
#pragma unroll
                for (int mi = 0; mi < 4; mi++)
#pragma unroll
                    for (int ni = 0; ni < 4; ni++) {
                        const int nb = ni >> 1, sE = ni & 1;
                        mma16816(acc[mi][ni], ah[mi], bh[nb][sE], bh[nb][sE + 2]);
                    }
            }
            __syncthreads();
        }

        // epilogue: frags -> smem, fused LSTM cell
        float* sC = (float*)smem;
#pragma unroll
        for (int mi = 0; mi < 4; mi++)
#pragma unroll
            for (int ni = 0; ni < 4; ni++) {
                int rr = wm * 64 + mi * 16 + (lane >> 2);
                int cidx = wn * 32 + ni * 8 + 2 * (lane & 3);
                sC[rr * 132 + cidx]           = acc[mi][ni][0];
                sC[rr * 132 + cidx + 1]       = acc[mi][ni][1];
                sC[(rr + 8) * 132 + cidx]     = acc[mi][ni][2];
                sC[(rr + 8) * 132 + cidx + 1] = acc[mi][ni][3];
            }
        __syncthreads();

        if (s == 0) {
            // c_old == 0: write c fresh, no read
#pragma unroll
            for (int it = 0; it < 16; it++) {
                int idx = tid + it * 256;
                int row = idx >> 5, ul = idx & 31;
                int mm = bm0 + row, ug = nt * 32 + ul;
                float iv = fsig(sC[row * 132 + ul * 4 + 0] + sB[ul * 4 + 0]);
                float gv = ftanh(sC[row * 132 + ul * 4 + 2] + sB[ul * 4 + 2]);
                float ov = fsig(sC[row * 132 + ul * 4 + 3] + sB[ul * 4 + 3]);
                float cv = iv * gv;
                g_c[mm * UNITS + ug] = cv;
                Hout[(size_t)mm * UNITS + ug] = __float2half_rn(ov * ftanh(cv));
            }
        } else {
#pragma unroll
            for (int it = 0; it < 16; it++) {
                int idx = tid + it * 256;
                int row = idx >> 5, ul = idx & 31;
                int mm = bm0 + row, ug = nt * 32 + ul;
                float iv = fsig(sC[row * 132 + ul * 4 + 0] + sB[ul * 4 + 0]);
                float fv = fsig(sC[row * 132 + ul * 4 + 1] + sB[ul * 4 + 1]);
                float gv = ftanh(sC[row * 132 + ul * 4 + 2] + sB[ul * 4 + 2]);
                float ov = fsig(sC[row * 132 + ul * 4 + 3] + sB[ul * 4 + 3]);
                float cv = fv * g_c[mm * UNITS + ug] + iv * gv;
                g_c[mm * UNITS + ug] = cv;
                Hout[(size_t)mm * UNITS + ug] = __float2half_rn(ov * ftanh(cv));
            }
        }

        __threadfence();   // release
        __syncthreads();
        if (tid == 0) atomicAdd(&g_cnt[s * MTILES + m], 1);
    }
}

// ---------------------------------------------------------------------------
// pred_all: one batched GEMM over the whole h-history (separate tail kernel).
// Rows r = s*BATCH + b (131072 rows), N=96, K=768, single-pass fp16, f32 acc.
// ---------------------------------------------------------------------------
__device__ __forceinline__ void load_pstage(uint32_t sb, int stage, int c, int tid,
                                            size_t abase) {
    uint32_t base = sb + stage * PSTG;
    int k0 = c * 64;
#pragma unroll
    for (int i = 0; i < 4; i++) {
        int e = tid + i * 256;
        int row = e >> 3, sub = e & 7;
        uint32_t off = row * 128 + sub * 16;
        uint32_t sw = off ^ ((off >> 3) & 0x70);
        cp16(base + P_A + sw, g_hist + abase + (size_t)row * UNITS + k0 + sub * 8);
    }
#pragma unroll
    for (int i = 0; i < 3; i++) {
        int e = tid + i * 256;
        int row = e >> 3, sub = e & 7;
        uint32_t off = row * 128 + sub * 16;
        uint32_t sw = off ^ ((off >> 3) & 0x70);
        cp16(base + P_BH + sw, g_Pdh + (size_t)row * UNITS + k0 + sub * 8);
    }
    asm volatile("cp.async.commit_group;");
}

__global__ __launch_bounds__(256) void pred_all(float* __restrict__ out,
                                                const float* __restrict__ b_d) {
    extern __shared__ __align__(1024) char smem[];
    const uint32_t sb = smem_u32(smem);
    const int tid = threadIdx.x;
    const int wid = tid >> 5;
    const int lane = tid & 31;
    const int bm0 = blockIdx.x * MT;
    const size_t abase = (size_t)bm0 * UNITS;

    const int wm = wid & 3, wn = wid >> 2;
    const int ra = lane & 7, qa = lane >> 3;
    const int colsel = (qa >> 1) * 16;
    int arow[2], axor[2], browr[3], bxor[3];
#pragma unroll
    for (int mi = 0; mi < 2; mi++) {
        int r = wm * 32 + mi * 16 + ra + (qa & 1) * 8;
        arow[mi] = r * 128;
        axor[mi] = (r & 7) << 4;
    }
#pragma unroll
    for (int nb = 0; nb < 3; nb++) {
        int r = wn * 48 + nb * 16 + ra + (qa & 1) * 8;
        browr[nb] = r * 128;
        bxor[nb] = (r & 7) << 4;
    }

    float acc[2][6][4];
#pragma unroll
    for (int mi = 0; mi < 2; mi++)
#pragma unroll
        for (int nj = 0; nj < 6; nj++)
#pragma unroll
            for (int j = 0; j < 4; j++) acc[mi][nj][j] = 0.0f;

    load_pstage(sb, 0, 0, tid, abase);

    int stage = 0;
#pragma unroll 1
    for (int c = 0; c < NCH_MAIN; c++) {
        if (c + 1 < NCH_MAIN) {
            load_pstage(sb, stage ^ 1, c + 1, tid, abase);
            asm volatile("cp.async.wait_group 1;");
        } else {
            asm volatile("cp.async.wait_group 0;");
        }
        __syncthreads();

        uint32_t base = sb + stage * PSTG;
#pragma unroll
        for (int kk = 0; kk < 4; kk++) {
            const int colb = kk * 32 + colsel;
            uint32_t ah[2][4], bh[3][4];
#pragma unroll
            for (int mi = 0; mi < 2; mi++)
                ldsm4(ah[mi], base + P_A + arow[mi] + (colb ^ axor[mi]));
#pragma unroll
            for (int nb = 0; nb < 3; nb++)
                ldsm4(bh[nb], base + P_BH + browr[nb] + (colb ^ bxor[nb]));
#pragma unroll
            for (int mi = 0; mi < 2; mi++)
#pragma unroll
                for (int nj = 0; nj < 6; nj++) {
                    const int nb = nj >> 1, sE = nj & 1;
                    mma16816(acc[mi][nj], ah[mi], bh[nb][sE], bh[nb][sE + 2]);
                }
        }
        __syncthreads();
        stage ^= 1;
    }

#pragma unroll
    for (int mi = 0; mi < 2; mi++)
#pragma unroll
        for (int nj = 0; nj < 6; nj++) {
            int r0 = bm0 + wm * 32 + mi * 16 + (lane >> 2);
            int cidx = wn * 48 + nj * 8 + 2 * (lane & 3);
            float b0v = b_d[cidx], b1v = b_d[cidx + 1];
#pragma unroll
            for (int half8 = 0; half8 < 2; half8++) {
                int r = r0 + half8 * 8;
                int b = r & (BATCH - 1);
                int s = r >> 11;
                size_t o = ((size_t)b * STEPS + s) * IND + cidx;
                out[o]     = acc[mi][nj][half8 * 2 + 0] + b0v;
                out[o + 1] = acc[mi][nj][half8 * 2 + 1] + b1v;
            }
        }
}

// ---------------------------------------------------------------------------
// Inputs: inputs, W_ih, W_hh, b_ih, b_hh, W_d, b_d
// ---------------------------------------------------------------------------
extern "C" void kernel_launch(void* const* d_in, const int* in_sizes, int n_in,
                              void* d_out, int out_size) {
    const float* inputs = (const float*)d_in[0];
    const float* W_ih   = (const float*)d_in[1];
    const float* W_hh   = (const float*)d_in[2];
    const float* b_ih   = (const float*)d_in[3];
    const float* b_hh   = (const float*)d_in[4];
    const float* W_d    = (const float*)d_in[5];
    const float* b_d    = (const float*)d_in[6];
    float* out = (float*)d_out;

    cudaFuncSetAttribute(run_persist,
                         cudaFuncAttributeMaxDynamicSharedMemorySize, GATES_SMEM);
    cudaFuncSetAttribute(pred_all,
                         cudaFuncAttributeMaxDynamicSharedMemorySize, PRED_SMEM);

    prep_all<<<(GATES * KP0 + 255) / 256, 256>>>(inputs, W_ih, b_ih, b_hh, W_d, b_d);
    run_persist<<<GRID_PERSIST, 256, GATES_SMEM>>>(W_ih, W_hh, W_d);
    pred_all<<<(BATCH * STEPS) / MT, 256, PRED_SMEM>>>(out, b_d);
}

// round 16
// speedup vs baseline: 1.0764x; 1.0764x over previous
#include <cuda_runtime.h>
#include <cuda_fp16.h>
#include <cstdint>
#include <math.h>

#define BATCH 2048
#define UNITS 768
#define IND   96
#define GATES 3072
#define STEPS 64
#define TIN   24

#define MT 128
#define NTILE 128          /* 32 units x 4 gates (reorder r' = u*4+q) */
#define MTILES 16
#define NTILES 24
#define TILES_PER_STEP (MTILES * NTILES)        /* 384 */
#define TOTAL_TICKETS (STEPS * TILES_PER_STEP)  /* 24576 */
#define GRID_PERSIST 296

#define KP_MAIN 768
#define NCH_MAIN 12
#define KP0 128
#define NCH0 2

/* gates smem: 3 stages x 32KB (A,B tiles of 16KB each) + bias */
#define STG_STRIDE 32768
#define T_AH 0
#define T_BH 16384
#define OFF_BIAS 98304
#define GATES_SMEM (OFF_BIAS + 512)     /* 98816 -> 2 CTAs/SM */

/* pred_all smem: 2 stages x 28KB (A 16KB + B 12KB) */
#define PSTG 28672
#define P_A  0
#define P_BH 16384
#define PRED_SMEM (2 * PSTG)            /* 57344 */

// ---------------------------------------------------------------------------
// Device globals
// ---------------------------------------------------------------------------
__device__ __half g_hist[(size_t)STEPS * BATCH * UNITS];  // h history
__device__ __half g_x0[BATCH * KP0];        // step-0 input, padded
__device__ float  g_c[BATCH * UNITS];       // cell state (cross-CTA: .cg only)
__device__ __half g_Weff[GATES * UNITS];    // reordered W_hh + W_ih@W_d (fp16)
__device__ __half g_Wih16[GATES * KP0];     // reordered W_ih (fp16, padded)
__device__ __half g_Pdh[IND * UNITS];       // W_d fp16 (row n, col k)
__device__ float  g_b0[GATES];              // reordered b_ih + b_hh
__device__ float  g_beff[GATES];            // reordered b_ih + b_hh + W_ih@b_d
__device__ int    g_ticket;                 // global tile ticket
__device__ int    g_cnt[STEPS * MTILES];    // per-(step, m-block) completion

__device__ __forceinline__ uint32_t smem_u32(const void* p) {
    uint32_t a;
    asm("{ .reg .u64 t; cvta.to.shared.u64 t, %1; cvt.u32.u64 %0, t; }" : "=r"(a) : "l"(p));
    return a;
}
__device__ __forceinline__ void cp16(uint32_t dst, const void* src) {
    asm volatile("cp.async.cg.shared.global [%0], [%1], 16;" :: "r"(dst), "l"(src));
}
__device__ __forceinline__ void ldsm4(uint32_t* r, uint32_t addr) {
    asm volatile("ldmatrix.sync.aligned.m8n8.x4.shared.b16 {%0,%1,%2,%3}, [%4];"
        : "=r"(r[0]), "=r"(r[1]), "=r"(r[2]), "=r"(r[3]) : "r"(addr));
}
__device__ __forceinline__ void mma16816(float* c, const uint32_t* a, uint32_t b0, uint32_t b1) {
    asm volatile("mma.sync.aligned.m16n8k16.row.col.f32.f16.f16.f32 "
        "{%0,%1,%2,%3}, {%4,%5,%6,%7}, {%8,%9}, {%0,%1,%2,%3};"
        : "+f"(c[0]), "+f"(c[1]), "+f"(c[2]), "+f"(c[3])
        : "r"(a[0]), "r"(a[1]), "r"(a[2]), "r"(a[3]), "r"(b0), "r"(b1));
}
__device__ __forceinline__ float sigm(float x) { return 1.0f / (1.0f + expf(-x)); }

// ---------------------------------------------------------------------------
// prep_all: scheduler init + x0 pad + c zero + W_ih fp16 + W_d fp16 + biases.
// GRID MUST COVER BATCH*UNITS (largest arm: g_c zeroing). R13/R14 sized it
// by GATES*KP0 and left 3/4 of g_c stale across replays -> the "divergence".
// ---------------------------------------------------------------------------
__global__ void prep_all(const float* __restrict__ inputs,
                         const float* __restrict__ W_ih,
                         const float* __restrict__ b_ih, const float* __restrict__ b_hh,
                         const float* __restrict__ W_d, const float* __restrict__ b_d) {
    int i = blockIdx.x * blockDim.x + threadIdx.x;
    if (i == 0) g_ticket = 0;
    if (i < STEPS * MTILES) g_cnt[i] = 0;
    if (i < BATCH * KP0) {
        int b = i / KP0, k = i % KP0;
        float v = (k < IND) ? inputs[(b * TIN + (TIN - 1)) * IND + k] : 0.0f;
        g_x0[i] = __float2half_rn(v);
    }
    if (i < BATCH * UNITS) g_c[i] = 0.0f;
    if (i < GATES * KP0) {
        int rp = i / KP0, k = i % KP0;
        int orig = (rp & 3) * UNITS + (rp >> 2);
        float w = (k < IND) ? W_ih[orig * IND + k] : 0.0f;
        g_Wih16[i] = __float2half_rn(w);
    }
    if (i < IND * UNITS) g_Pdh[i] = __float2half_rn(W_d[i]);
    if (i < GATES) {
        int orig = (i & 3) * UNITS + (i >> 2);
        float b0 = b_ih[orig] + b_hh[orig];
        g_b0[i] = b0;
        float be = b0;
#pragma unroll 4
        for (int j = 0; j < IND; j++) be += W_ih[orig * IND + j] * b_d[j];
        g_beff[i] = be;
    }
}

// prep_weff: W_eff = W_hh + W_ih @ W_d  (fp32 compute, fp16 store, reordered)
__global__ void prep_weff(const float* __restrict__ W_ih, const float* __restrict__ W_hh,
                          const float* __restrict__ W_d) {
    int i = blockIdx.x * blockDim.x + threadIdx.x;
    if (i >= GATES * UNITS) return;
    int rp = i / UNITS, k = i % UNITS;
    int orig = (rp & 3) * UNITS + (rp >> 2);
    float s = W_hh[orig * UNITS + k];
#pragma unroll 4
    for (int j = 0; j < IND; j++) s += W_ih[orig * IND + j] * W_d[j * UNITS + k];
    g_Weff[i] = __float2half_rn(s);
}

// ---------------------------------------------------------------------------
// gates_persist: persistent kernel, global ticket queue over all 64 steps.
// g_c accesses use .cg (L2 path) — hardening against cross-SM L1 staleness.
// ---------------------------------------------------------------------------
__device__ __forceinline__ void load_stage_r(uint32_t sb, int stage, int kc, int tid,
                                             int bm0, int n0r, int kp,
                                             const __half* __restrict__ A,
                                             const __half* __restrict__ W) {
    uint32_t base = sb + stage * STG_STRIDE;
    int k0 = kc * 64;   // halves
#pragma unroll
    for (int i = 0; i < 4; i++) {
        int e = tid + i * 256;
        int row = e >> 3, sub = e & 7;
        uint32_t off = row * 128 + sub * 16;
        uint32_t sw = off ^ ((off >> 3) & 0x70);
        cp16(base + T_AH + sw, A + (size_t)(bm0 + row) * kp + k0 + sub * 8);
        cp16(base + T_BH + sw, W + (size_t)(n0r + row) * kp + k0 + sub * 8);
    }
    asm volatile("cp.async.commit_group;");
}

__global__ __launch_bounds__(256) void gates_persist() {
    extern __shared__ __align__(1024) char smem[];
    __shared__ int s_ticket;
    const uint32_t sb = smem_u32(smem);
    float* sB = (float*)(smem + OFF_BIAS);
    const int tid = threadIdx.x;
    const int wid = tid >> 5;
    const int lane = tid & 31;

    // warp tiling: 2 (m) x 4 (n); warp tile 64 x 32
    const int wm = wid & 1, wn = wid >> 1;
    const int ra = lane & 7, qa = lane >> 3;
    const int colsel = (qa >> 1) * 16;
    int arow[4], axor[4], browr[2], bxor[2];
#pragma unroll
    for (int mi = 0; mi < 4; mi++) {
        int r = wm * 64 + mi * 16 + ra + (qa & 1) * 8;
        arow[mi] = r * 128;
        axor[mi] = (r & 7) << 4;
    }
#pragma unroll
    for (int nb = 0; nb < 2; nb++) {
        int r = wn * 32 + nb * 16 + ra + (qa & 1) * 8;
        browr[nb] = r * 128;
        bxor[nb] = (r & 7) << 4;
    }

    for (;;) {
        if (tid == 0) s_ticket = atomicAdd(&g_ticket, 1);
        __syncthreads();
        const int ticket = s_ticket;
        if (ticket >= TOTAL_TICKETS) break;

        const int s  = ticket / TILES_PER_STEP;
        const int t  = ticket % TILES_PER_STEP;
        const int m  = t / NTILES;          // m-major: aligns with producers
        const int nt = t % NTILES;
        const int bm0 = m * MT;
        const int n0r = nt * NTILE;

        const __half* A; const __half* W; const float* bias;
        int kp, nch;
        if (s == 0) { A = g_x0; W = g_Wih16; bias = g_b0; kp = KP0; nch = NCH0; }
        else {
            A = g_hist + (size_t)(s - 1) * BATCH * UNITS;
            W = g_Weff; bias = g_beff; kp = KP_MAIN; nch = NCH_MAIN;
        }
        __half* __restrict__ Hout = g_hist + (size_t)s * BATCH * UNITS;

        // dependency: all 24 producers of h[s-1, m-block] complete
        if (s > 0) {
            if (tid == 0) {
                volatile int* c = &g_cnt[(s - 1) * MTILES + m];
                while (*c < NTILES) __nanosleep(64);
            }
            __syncthreads();
            __threadfence();   // acquire
        }

        if (tid < NTILE) sB[tid] = bias[n0r + tid];

        float acc[4][4][4];
#pragma unroll
        for (int mi = 0; mi < 4; mi++)
#pragma unroll
            for (int ni = 0; ni < 4; ni++)
#pragma unroll
                for (int j = 0; j < 4; j++) acc[mi][ni][j] = 0.0f;

        load_stage_r(sb, 0, 0, tid, bm0, n0r, kp, A, W);
        load_stage_r(sb, 1, 1, tid, bm0, n0r, kp, A, W);

#pragma unroll 1
        for (int i = 0; i < nch; i++) {
            if (i + 2 < nch) {
                load_stage_r(sb, (i + 2) % 3, i + 2, tid, bm0, n0r, kp, A, W);
                asm volatile("cp.async.wait_group 2;");
            } else if (i + 1 < nch) {
                asm volatile("cp.async.wait_group 1;");
            } else {
                asm volatile("cp.async.wait_group 0;");
            }
            __syncthreads();

            uint32_t base = sb + (i % 3) * STG_STRIDE;
#pragma unroll
            for (int kk = 0; kk < 4; kk++) {
                const int colb = kk * 32 + colsel;
                uint32_t ah[4][4], bh[2][4];
#pragma unroll
                for (int mi = 0; mi < 4; mi++)
                    ldsm4(ah[mi], base + T_AH + arow[mi] + (colb ^ axor[mi]));
#pragma unroll
                for (int nb = 0; nb < 2; nb++)
                    ldsm4(bh[nb], base + T_BH + browr[nb] + (colb ^ bxor[nb]));
#pragma unroll
                for (int mi = 0; mi < 4; mi++)
#pragma unroll
                    for (int ni = 0; ni < 4; ni++) {
                        const int nb = ni >> 1, sE = ni & 1;
                        mma16816(acc[mi][ni], ah[mi], bh[nb][sE], bh[nb][sE + 2]);
                    }
            }
            __syncthreads();
        }

        // ---- epilogue: frags -> smem, fused LSTM cell ----
        float* sC = (float*)smem;   // [128][132] = 67584 B < 98304
#pragma unroll
        for (int mi = 0; mi < 4; mi++)
#pragma unroll
            for (int ni = 0; ni < 4; ni++) {
                int r = wm * 64 + mi * 16 + (lane >> 2);
                int cidx = wn * 32 + ni * 8 + 2 * (lane & 3);
                sC[r * 132 + cidx]           = acc[mi][ni][0];
                sC[r * 132 + cidx + 1]       = acc[mi][ni][1];
                sC[(r + 8) * 132 + cidx]     = acc[mi][ni][2];
                sC[(r + 8) * 132 + cidx + 1] = acc[mi][ni][3];
            }
        __syncthreads();

#pragma unroll
        for (int it = 0; it < 16; it++) {
            int idx = tid + it * 256;
            int row = idx >> 5, ul = idx & 31;
            int mm = bm0 + row, ug = nt * 32 + ul;
            float iv = sigm(sC[row * 132 + ul * 4 + 0] + sB[ul * 4 + 0]);
            float fv = sigm(sC[row * 132 + ul * 4 + 1] + sB[ul * 4 + 1]);
            float gv = tanhf(sC[row * 132 + ul * 4 + 2] + sB[ul * 4 + 2]);
            float ov = sigm(sC[row * 132 + ul * 4 + 3] + sB[ul * 4 + 3]);
            float cold = __ldcg(&g_c[mm * UNITS + ug]);   // L2 path
            float cv = fv * cold + iv * gv;
            __stcg(&g_c[mm * UNITS + ug], cv);
            float hv = ov * tanhf(cv);
            Hout[(size_t)mm * UNITS + ug] = __float2half_rn(hv);
        }

        __threadfence();        // release: publish h + c before counting
        __syncthreads();
        if (tid == 0) atomicAdd(&g_cnt[s * MTILES + m], 1);
    }
}

// ---------------------------------------------------------------------------
// pred_all: one batched GEMM over the whole h-history.
// ---------------------------------------------------------------------------
__device__ __forceinline__ void load_pstage(uint32_t sb, int stage, int c, int tid,
                                            size_t abase) {
    uint32_t base = sb + stage * PSTG;
    int k0 = c * 64;
#pragma unroll
    for (int i = 0; i < 4; i++) {      // A: 128 rows
        int e = tid + i * 256;
        int row = e >> 3, sub = e & 7;
        uint32_t off = row * 128 + sub * 16;
        uint32_t sw = off ^ ((off >> 3) & 0x70);
        cp16(base + P_A + sw, g_hist + abase + (size_t)row * UNITS + k0 + sub * 8);
    }
#pragma unroll
    for (int i = 0; i < 3; i++) {      // B: 96 rows
        int e = tid + i * 256;
        int row = e >> 3, sub = e & 7;
        uint32_t off = row * 128 + sub * 16;
        uint32_t sw = off ^ ((off >> 3) & 0x70);
        cp16(base + P_BH + sw, g_Pdh + (size_t)row * UNITS + k0 + sub * 8);
    }
    asm volatile("cp.async.commit_group;");
}

__global__ __launch_bounds__(256) void pred_all(float* __restrict__ out,
                                                const float* __restrict__ b_d) {
    extern __shared__ __align__(1024) char smem[];
    const uint32_t sb = smem_u32(smem);
    const int tid = threadIdx.x;
    const int wid = tid >> 5;
    const int lane = tid & 31;
    const int bm0 = blockIdx.x * MT;
    const size_t abase = (size_t)bm0 * UNITS;

    const int wm = wid & 3, wn = wid >> 2;
    const int ra = lane & 7, qa = lane >> 3;
    const int colsel = (qa >> 1) * 16;
    int arow[2], axor[2], browr[3], bxor[3];
#pragma unroll
    for (int mi = 0; mi < 2; mi++) {
        int r = wm * 32 + mi * 16 + ra + (qa & 1) * 8;
        arow[mi] = r * 128;
        axor[mi] = (r & 7) << 4;
    }
#pragma unroll
    for (int nb = 0; nb < 3; nb++) {
        int r = wn * 48 + nb * 16 + ra + (qa & 1) * 8;
        browr[nb] = r * 128;
        bxor[nb] = (r & 7) << 4;
    }

    float acc[2][6][4];
#pragma unroll
    for (int mi = 0; mi < 2; mi++)
#pragma unroll
        for (int nj = 0; nj < 6; nj++)
#pragma unroll
            for (int j = 0; j < 4; j++) acc[mi][nj][j] = 0.0f;

    load_pstage(sb, 0, 0, tid, abase);

    int stage = 0;
#pragma unroll 1
    for (int c = 0; c < NCH_MAIN; c++) {
        if (c + 1 < NCH_MAIN) {
            load_pstage(sb, stage ^ 1, c + 1, tid, abase);
            asm volatile("cp.async.wait_group 1;");
        } else {
            asm volatile("cp.async.wait_group 0;");
        }
        __syncthreads();

        uint32_t base = sb + stage * PSTG;
#pragma unroll
        for (int kk = 0; kk < 4; kk++) {
            const int colb = kk * 32 + colsel;
            uint32_t ah[2][4], bh[3][4];
#pragma unroll
            for (int mi = 0; mi < 2; mi++)
                ldsm4(ah[mi], base + P_A + arow[mi] + (colb ^ axor[mi]));
#pragma unroll
            for (int nb = 0; nb < 3; nb++)
                ldsm4(bh[nb], base + P_BH + browr[nb] + (colb ^ bxor[nb]));
#pragma unroll
            for (int mi = 0; mi < 2; mi++)
#pragma unroll
                for (int nj = 0; nj < 6; nj++) {
                    const int nb = nj >> 1, sE = nj & 1;
                    mma16816(acc[mi][nj], ah[mi], bh[nb][sE], bh[nb][sE + 2]);
                }
        }
        __syncthreads();
        stage ^= 1;
    }

#pragma unroll
    for (int mi = 0; mi < 2; mi++)
#pragma unroll
        for (int nj = 0; nj < 6; nj++) {
            int r0 = bm0 + wm * 32 + mi * 16 + (lane >> 2);
            int cidx = wn * 48 + nj * 8 + 2 * (lane & 3);
            float b0v = b_d[cidx], b1v = b_d[cidx + 1];
#pragma unroll
            for (int half8 = 0; half8 < 2; half8++) {
                int r = r0 + half8 * 8;
                int b = r & (BATCH - 1);
                int s = r >> 11;
                size_t o = ((size_t)b * STEPS + s) * IND + cidx;
                out[o]     = acc[mi][nj][half8 * 2 + 0] + b0v;
                out[o + 1] = acc[mi][nj][half8 * 2 + 1] + b1v;
            }
        }
}

// ---------------------------------------------------------------------------
// Inputs: inputs, W_ih, W_hh, b_ih, b_hh, W_d, b_d
// ---------------------------------------------------------------------------
extern "C" void kernel_launch(void* const* d_in, const int* in_sizes, int n_in,
                              void* d_out, int out_size) {
    const float* inputs = (const float*)d_in[0];
    const float* W_ih   = (const float*)d_in[1];
    const float* W_hh   = (const float*)d_in[2];
    const float* b_ih   = (const float*)d_in[3];
    const float* b_hh   = (const float*)d_in[4];
    const float* W_d    = (const float*)d_in[5];
    const float* b_d    = (const float*)d_in[6];
    float* out = (float*)d_out;

    cudaFuncSetAttribute(gates_persist,
                         cudaFuncAttributeMaxDynamicSharedMemorySize, GATES_SMEM);
    cudaFuncSetAttribute(pred_all,
                         cudaFuncAttributeMaxDynamicSharedMemorySize, PRED_SMEM);

    // grid must cover the largest arm: BATCH*UNITS (g_c zeroing)
    prep_all<<<(BATCH * UNITS + 255) / 256, 256>>>(inputs, W_ih, b_ih, b_hh, W_d, b_d);
    prep_weff<<<(GATES * UNITS + 255) / 256, 256>>>(W_ih, W_hh, W_d);

    gates_persist<<<GRID_PERSIST, 256, GATES_SMEM>>>();

    pred_all<<<(BATCH * STEPS) / MT, 256, PRED_SMEM>>>(out, b_d);
}

// round 17
// speedup vs baseline: 1.1284x; 1.0483x over previous
#include <cuda_runtime.h>
#include <cuda_fp16.h>
#include <cstdint>
#include <math.h>

#define BATCH 2048
#define UNITS 768
#define IND   96
#define GATES 3072
#define STEPS 64
#define TIN   24

#define MT 128
#define NTILE 128          /* 32 units x 4 gates (reorder r' = u*4+q) */
#define MTILES 16
#define NTILES 24
#define TILES_PER_STEP (MTILES * NTILES)        /* 384 */
#define TOTAL_TICKETS (STEPS * TILES_PER_STEP)  /* 24576 */
#define GRID_PERSIST 296

#define KP_MAIN 768
#define NCH_MAIN 12
#define KP0 128
#define NCH0 2

/* gates smem: 3 stages x 32KB (A,B tiles of 16KB each) + bias */
#define STG_STRIDE 32768
#define T_AH 0
#define T_BH 16384
#define OFF_BIAS 98304
#define GATES_SMEM (OFF_BIAS + 512)     /* 98816 -> 2 CTAs/SM */

/* pred_all smem: 3 stages x 28KB (A 16KB + B 12KB) */
#define PSTG 28672
#define P_A  0
#define P_BH 16384
#define PRED_SMEM (3 * PSTG)            /* 86016 */

// ---------------------------------------------------------------------------
// Device globals
// ---------------------------------------------------------------------------
__device__ __half g_hist[(size_t)STEPS * BATCH * UNITS];  // h history
__device__ __half g_x0[BATCH * KP0];        // step-0 input, padded
__device__ float  g_c[BATCH * UNITS];       // cell state (cross-CTA: .cg only)
__device__ __half g_Weff[GATES * UNITS];    // reordered W_hh + W_ih@W_d (fp16)
__device__ __half g_Wih16[GATES * KP0];     // reordered W_ih (fp16, padded)
__device__ __half g_Pdh[IND * UNITS];       // W_d fp16 (row n, col k)
__device__ float  g_b0[GATES];              // reordered b_ih + b_hh
__device__ float  g_beff[GATES];            // reordered b_ih + b_hh + W_ih@b_d
__device__ int    g_ticket;                 // global tile ticket
__device__ int    g_cnt[STEPS * MTILES];    // per-(step, m-block) completion

__device__ __forceinline__ uint32_t smem_u32(const void* p) {
    uint32_t a;
    asm("{ .reg .u64 t; cvta.to.shared.u64 t, %1; cvt.u32.u64 %0, t; }" : "=r"(a) : "l"(p));
    return a;
}
__device__ __forceinline__ void cp16(uint32_t dst, const void* src) {
    asm volatile("cp.async.cg.shared.global [%0], [%1], 16;" :: "r"(dst), "l"(src));
}
__device__ __forceinline__ void ldsm4(uint32_t* r, uint32_t addr) {
    asm volatile("ldmatrix.sync.aligned.m8n8.x4.shared.b16 {%0,%1,%2,%3}, [%4];"
        : "=r"(r[0]), "=r"(r[1]), "=r"(r[2]), "=r"(r[3]) : "r"(addr));
}
__device__ __forceinline__ void mma16816(float* c, const uint32_t* a, uint32_t b0, uint32_t b1) {
    asm volatile("mma.sync.aligned.m16n8k16.row.col.f32.f16.f16.f32 "
        "{%0,%1,%2,%3}, {%4,%5,%6,%7}, {%8,%9}, {%0,%1,%2,%3};"
        : "+f"(c[0]), "+f"(c[1]), "+f"(c[2]), "+f"(c[3])
        : "r"(a[0]), "r"(a[1]), "r"(a[2]), "r"(a[3]), "r"(b0), "r"(b1));
}
// fast transcendentals (MUFU-backed; rel err ~1e-6 — proven in R10/R11)
__device__ __forceinline__ float fsig(float x)  { return __fdividef(1.0f, 1.0f + __expf(-x)); }
__device__ __forceinline__ float ftanh(float x) {
    float e = __expf(2.0f * x);
    return __fdividef(e - 1.0f, e + 1.0f);
}

// ---------------------------------------------------------------------------
// prep_all: scheduler init + x0 pad + c zero + W_ih fp16 + W_d fp16 + biases.
// GRID MUST COVER BATCH*UNITS (largest arm: g_c zeroing).
// ---------------------------------------------------------------------------
__global__ void prep_all(const float* __restrict__ inputs,
                         const float* __restrict__ W_ih,
                         const float* __restrict__ b_ih, const float* __restrict__ b_hh,
                         const float* __restrict__ W_d, const float* __restrict__ b_d) {
    int i = blockIdx.x * blockDim.x + threadIdx.x;
    if (i == 0) g_ticket = 0;
    if (i < STEPS * MTILES) g_cnt[i] = 0;
    if (i < BATCH * KP0) {
        int b = i / KP0, k = i % KP0;
        float v = (k < IND) ? inputs[(b * TIN + (TIN - 1)) * IND + k] : 0.0f;
        g_x0[i] = __float2half_rn(v);
    }
    if (i < BATCH * UNITS) g_c[i] = 0.0f;
    if (i < GATES * KP0) {
        int rp = i / KP0, k = i % KP0;
        int orig = (rp & 3) * UNITS + (rp >> 2);
        float w = (k < IND) ? W_ih[orig * IND + k] : 0.0f;
        g_Wih16[i] = __float2half_rn(w);
    }
    if (i < IND * UNITS) g_Pdh[i] = __float2half_rn(W_d[i]);
    if (i < GATES) {
        int orig = (i & 3) * UNITS + (i >> 2);
        float b0 = b_ih[orig] + b_hh[orig];
        g_b0[i] = b0;
        float be = b0;
#pragma unroll 4
        for (int j = 0; j < IND; j++) be += W_ih[orig * IND + j] * b_d[j];
        g_beff[i] = be;
    }
}

// prep_weff: W_eff = W_hh + W_ih @ W_d  (fp32 compute, fp16 store, reordered)
__global__ void prep_weff(const float* __restrict__ W_ih, const float* __restrict__ W_hh,
                          const float* __restrict__ W_d) {
    int i = blockIdx.x * blockDim.x + threadIdx.x;
    if (i >= GATES * UNITS) return;
    int rp = i / UNITS, k = i % UNITS;
    int orig = (rp & 3) * UNITS + (rp >> 2);
    float s = W_hh[orig * UNITS + k];
#pragma unroll 4
    for (int j = 0; j < IND; j++) s += W_ih[orig * IND + j] * W_d[j * UNITS + k];
    g_Weff[i] = __float2half_rn(s);
}

// ---------------------------------------------------------------------------
// gates_persist: persistent kernel, global ticket queue over all 64 steps.
// ---------------------------------------------------------------------------
__device__ __forceinline__ void load_stage_r(uint32_t sb, int stage, int kc, int tid,
                                             int bm0, int n0r, int kp,
                                             const __half* __restrict__ A,
                                             const __half* __restrict__ W) {
    uint32_t base = sb + stage * STG_STRIDE;
    int k0 = kc * 64;   // halves
#pragma unroll
    for (int i = 0; i < 4; i++) {
        int e = tid + i * 256;
        int row = e >> 3, sub = e & 7;
        uint32_t off = row * 128 + sub * 16;
        uint32_t sw = off ^ ((off >> 3) & 0x70);
        cp16(base + T_AH + sw, A + (size_t)(bm0 + row) * kp + k0 + sub * 8);
        cp16(base + T_BH + sw, W + (size_t)(n0r + row) * kp + k0 + sub * 8);
    }
    asm volatile("cp.async.commit_group;");
}

__global__ __launch_bounds__(256) void gates_persist() {
    extern __shared__ __align__(1024) char smem[];
    __shared__ int s_ticket;
    const uint32_t sb = smem_u32(smem);
    float* sB = (float*)(smem + OFF_BIAS);
    const int tid = threadIdx.x;
    const int wid = tid >> 5;
    const int lane = tid & 31;

    // warp tiling: 2 (m) x 4 (n); warp tile 64 x 32
    const int wm = wid & 1, wn = wid >> 1;
    const int ra = lane & 7, qa = lane >> 3;
    const int colsel = (qa >> 1) * 16;
    int arow[4], axor[4], browr[2], bxor[2];
#pragma unroll
    for (int mi = 0; mi < 4; mi++) {
        int r = wm * 64 + mi * 16 + ra + (qa & 1) * 8;
        arow[mi] = r * 128;
        axor[mi] = (r & 7) << 4;
    }
#pragma unroll
    for (int nb = 0; nb < 2; nb++) {
        int r = wn * 32 + nb * 16 + ra + (qa & 1) * 8;
        browr[nb] = r * 128;
        bxor[nb] = (r & 7) << 4;
    }

    for (;;) {
        if (tid == 0) s_ticket = atomicAdd(&g_ticket, 1);
        __syncthreads();
        const int ticket = s_ticket;
        if (ticket >= TOTAL_TICKETS) break;

        const int s  = ticket / TILES_PER_STEP;
        const int t  = ticket % TILES_PER_STEP;
        const int m  = t / NTILES;          // m-major: aligns with producers
        const int nt = t % NTILES;
        const int bm0 = m * MT;
        const int n0r = nt * NTILE;

        const __half* A; const __half* W; const float* bias;
        int kp, nch;
        if (s == 0) { A = g_x0; W = g_Wih16; bias = g_b0; kp = KP0; nch = NCH0; }
        else {
            A = g_hist + (size_t)(s - 1) * BATCH * UNITS;
            W = g_Weff; bias = g_beff; kp = KP_MAIN; nch = NCH_MAIN;
        }
        __half* __restrict__ Hout = g_hist + (size_t)s * BATCH * UNITS;

        // dependency: all 24 producers of h[s-1, m-block] complete
        if (s > 0) {
            if (tid == 0) {
                volatile int* c = &g_cnt[(s - 1) * MTILES + m];
                while (*c < NTILES) __nanosleep(64);
            }
            __syncthreads();
            __threadfence();   // acquire
        }

        if (tid < NTILE) sB[tid] = bias[n0r + tid];

        float acc[4][4][4];
#pragma unroll
        for (int mi = 0; mi < 4; mi++)
#pragma unroll
            for (int ni = 0; ni < 4; ni++)
#pragma unroll
                for (int j = 0; j < 4; j++) acc[mi][ni][j] = 0.0f;

        load_stage_r(sb, 0, 0, tid, bm0, n0r, kp, A, W);
        load_stage_r(sb, 1, 1, tid, bm0, n0r, kp, A, W);

#pragma unroll 1
        for (int i = 0; i < nch; i++) {
            if (i + 2 < nch) {
                load_stage_r(sb, (i + 2) % 3, i + 2, tid, bm0, n0r, kp, A, W);
                asm volatile("cp.async.wait_group 2;");
            } else if (i + 1 < nch) {
                asm volatile("cp.async.wait_group 1;");
            } else {
                asm volatile("cp.async.wait_group 0;");
            }
            __syncthreads();

            uint32_t base = sb + (i % 3) * STG_STRIDE;
#pragma unroll
            for (int kk = 0; kk < 4; kk++) {
                const int colb = kk * 32 + colsel;
                uint32_t ah[4][4], bh[2][4];
#pragma unroll
                for (int mi = 0; mi < 4; mi++)
                    ldsm4(ah[mi], base + T_AH + arow[mi] + (colb ^ axor[mi]));
#pragma unroll
                for (int nb = 0; nb < 2; nb++)
                    ldsm4(bh[nb], base + T_BH + browr[nb] + (colb ^ bxor[nb]));
#pragma unroll
                for (int mi = 0; mi < 4; mi++)
#pragma unroll
                    for (int ni = 0; ni < 4; ni++) {
                        const int nb = ni >> 1, sE = ni & 1;
                        mma16816(acc[mi][ni], ah[mi], bh[nb][sE], bh[nb][sE + 2]);
                    }
            }
            __syncthreads();
        }

        // ---- epilogue: frags -> smem, fused LSTM cell ----
        float* sC = (float*)smem;   // [128][132] = 67584 B < 98304
#pragma unroll
        for (int mi = 0; mi < 4; mi++)
#pragma unroll
            for (int ni = 0; ni < 4; ni++) {
                int r = wm * 64 + mi * 16 + (lane >> 2);
                int cidx = wn * 32 + ni * 8 + 2 * (lane & 3);
                sC[r * 132 + cidx]           = acc[mi][ni][0];
                sC[r * 132 + cidx + 1]       = acc[mi][ni][1];
                sC[(r + 8) * 132 + cidx]     = acc[mi][ni][2];
                sC[(r + 8) * 132 + cidx + 1] = acc[mi][ni][3];
            }
        __syncthreads();

#pragma unroll
        for (int it = 0; it < 16; it++) {
            int idx = tid + it * 256;
            int row = idx >> 5, ul = idx & 31;
            int mm = bm0 + row, ug = nt * 32 + ul;
            float iv = fsig(sC[row * 132 + ul * 4 + 0] + sB[ul * 4 + 0]);
            float fv = fsig(sC[row * 132 + ul * 4 + 1] + sB[ul * 4 + 1]);
            float gv = ftanh(sC[row * 132 + ul * 4 + 2] + sB[ul * 4 + 2]);
            float ov = fsig(sC[row * 132 + ul * 4 + 3] + sB[ul * 4 + 3]);
            float cold = __ldcg(&g_c[mm * UNITS + ug]);   // L2 path
            float cv = fv * cold + iv * gv;
            __stcg(&g_c[mm * UNITS + ug], cv);
            float hv = ov * ftanh(cv);
            Hout[(size_t)mm * UNITS + ug] = __float2half_rn(hv);
        }

        __threadfence();        // release: publish h + c before counting
        __syncthreads();
        if (tid == 0) atomicAdd(&g_cnt[s * MTILES + m], 1);
    }
}

// ---------------------------------------------------------------------------
// pred_all: one batched GEMM over the whole h-history. 3-stage pipeline
// (DRAM-bound at 40% of peak with 2 stages; deeper MLP raises throughput).
// ---------------------------------------------------------------------------
__device__ __forceinline__ void load_pstage(uint32_t sb, int stage, int c, int tid,
                                            size_t abase) {
    uint32_t base = sb + stage * PSTG;
    int k0 = c * 64;
#pragma unroll
    for (int i = 0; i < 4; i++) {      // A: 128 rows
        int e = tid + i * 256;
        int row = e >> 3, sub = e & 7;
        uint32_t off = row * 128 + sub * 16;
        uint32_t sw = off ^ ((off >> 3) & 0x70);
        cp16(base + P_A + sw, g_hist + abase + (size_t)row * UNITS + k0 + sub * 8);
    }
#pragma unroll
    for (int i = 0; i < 3; i++) {      // B: 96 rows
        int e = tid + i * 256;
        int row = e >> 3, sub = e & 7;
        uint32_t off = row * 128 + sub * 16;
        uint32_t sw = off ^ ((off >> 3) & 0x70);
        cp16(base + P_BH + sw, g_Pdh + (size_t)row * UNITS + k0 + sub * 8);
    }
    asm volatile("cp.async.commit_group;");
}

__global__ __launch_bounds__(256) void pred_all(float* __restrict__ out,
                                                const float* __restrict__ b_d) {
    extern __shared__ __align__(1024) char smem[];
    const uint32_t sb = smem_u32(smem);
    const int tid = threadIdx.x;
    const int wid = tid >> 5;
    const int lane = tid & 31;
    const int bm0 = blockIdx.x * MT;
    const size_t abase = (size_t)bm0 * UNITS;

    const int wm = wid & 3, wn = wid >> 2;
    const int ra = lane & 7, qa = lane >> 3;
    const int colsel = (qa >> 1) * 16;
    int arow[2], axor[2], browr[3], bxor[3];
#pragma unroll
    for (int mi = 0; mi < 2; mi++) {
        int r = wm * 32 + mi * 16 + ra + (qa & 1) * 8;
        arow[mi] = r * 128;
        axor[mi] = (r & 7) << 4;
    }
#pragma unroll
    for (int nb = 0; nb < 3; nb++) {
        int r = wn * 48 + nb * 16 + ra + (qa & 1) * 8;
        browr[nb] = r * 128;
        bxor[nb] = (r & 7) << 4;
    }

    float acc[2][6][4];
#pragma unroll
    for (int mi = 0; mi < 2; mi++)
#pragma unroll
        for (int nj = 0; nj < 6; nj++)
#pragma unroll
            for (int j = 0; j < 4; j++) acc[mi][nj][j] = 0.0f;

    load_pstage(sb, 0, 0, tid, abase);
    load_pstage(sb, 1, 1, tid, abase);

#pragma unroll 1
    for (int c = 0; c < NCH_MAIN; c++) {
        if (c + 2 < NCH_MAIN) {
            load_pstage(sb, (c + 2) % 3, c + 2, tid, abase);
            asm volatile("cp.async.wait_group 2;");
        } else if (c + 1 < NCH_MAIN) {
            asm volatile("cp.async.wait_group 1;");
        } else {
            asm volatile("cp.async.wait_group 0;");
        }
        __syncthreads();

        uint32_t base = sb + (c % 3) * PSTG;
#pragma unroll
        for (int kk = 0; kk < 4; kk++) {
            const int colb = kk * 32 + colsel;
            uint32_t ah[2][4], bh[3][4];
#pragma unroll
            for (int mi = 0; mi < 2; mi++)
                ldsm4(ah[mi], base + P_A + arow[mi] + (colb ^ axor[mi]));
#pragma unroll
            for (int nb = 0; nb < 3; nb++)
                ldsm4(bh[nb], base + P_BH + browr[nb] + (colb ^ bxor[nb]));
#pragma unroll
            for (int mi = 0; mi < 2; mi++)
#pragma unroll
                for (int nj = 0; nj < 6; nj++) {
                    const int nb = nj >> 1, sE = nj & 1;
                    mma16816(acc[mi][nj], ah[mi], bh[nb][sE], bh[nb][sE + 2]);
                }
        }
        __syncthreads();
    }

#pragma unroll
    for (int mi = 0; mi < 2; mi++)
#pragma unroll
        for (int nj = 0; nj < 6; nj++) {
            int r0 = bm0 + wm * 32 + mi * 16 + (lane >> 2);
            int cidx = wn * 48 + nj * 8 + 2 * (lane & 3);
            float b0v = b_d[cidx], b1v = b_d[cidx + 1];
#pragma unroll
            for (int half8 = 0; half8 < 2; half8++) {
                int r = r0 + half8 * 8;
                int b = r & (BATCH - 1);
                int s = r >> 11;
                size_t o = ((size_t)b * STEPS + s) * IND + cidx;
                out[o]     = acc[mi][nj][half8 * 2 + 0] + b0v;
                out[o + 1] = acc[mi][nj][half8 * 2 + 1] + b1v;
            }
        }
}

// ---------------------------------------------------------------------------
// Inputs: inputs, W_ih, W_hh, b_ih, b_hh, W_d, b_d
// ---------------------------------------------------------------------------
extern "C" void kernel_launch(void* const* d_in, const int* in_sizes, int n_in,
                              void* d_out, int out_size) {
    const float* inputs = (const float*)d_in[0];
    const float* W_ih   = (const float*)d_in[1];
    const float* W_hh   = (const float*)d_in[2];
    const float* b_ih   = (const float*)d_in[3];
    const float* b_hh   = (const float*)d_in[4];
    const float* W_d    = (const float*)d_in[5];
    const float* b_d    = (const float*)d_in[6];
    float* out = (float*)d_out;

    cudaFuncSetAttribute(gates_persist,
                         cudaFuncAttributeMaxDynamicSharedMemorySize, GATES_SMEM);
    cudaFuncSetAttribute(pred_all,
                         cudaFuncAttributeMaxDynamicSharedMemorySize, PRED_SMEM);

    // grid must cover the largest arm: BATCH*UNITS (g_c zeroing)
    prep_all<<<(BATCH * UNITS + 255) / 256, 256>>>(inputs, W_ih, b_ih, b_hh, W_d, b_d);
    prep_weff<<<(GATES * UNITS + 255) / 256, 256>>>(W_ih, W_hh, W_d);

    gates_persist<<<GRID_PERSIST, 256, GATES_SMEM>>>();

    pred_all<<<(BATCH * STEPS) / MT, 256, PRED_SMEM>>>(out, b_d);
}